// round 3
// baseline (speedup 1.0000x reference)
#include <cuda_runtime.h>
#include <math.h>

#define BB 128
#define TT 512
#define HH 1024
#define EE 128
#define NL 17
#define G3 3072        // 3*HH
#define NCTA 128       // persistent CTAs (<=148 SMs -> co-resident)
#define KC 64          // K-block for recurrent GEMM
#define SHP 66         // padded shared row stride (conflict-free float2 reads)

// ---------------- device scratch (no cudaMalloc allowed) ----------------
__device__ float g_gxw[201326592];            // [B][T][3H] precomputed w-part of gx
__device__ float g_tbl[NL * G3];              // label_emb @ W_ih[:, :E]^T + b_ih
__device__ float g_hbuf[2][BB * HH];          // double-buffered hidden state
__device__ volatile unsigned g_pt[BB];        // packed (tag<<5)|pred per batch
__device__ volatile unsigned g_flags[NCTA];   // flat barrier flags (epoch values)

// ---------------- helpers ----------------
__device__ __forceinline__ float sigmoidf_(float x) { return 1.0f / (1.0f + expf(-x)); }

// IOBES transition mask. Labels: 0="O", 1+4*type+p with p: B=0,I=1,E=2,S=3.
__device__ __forceinline__ float maskval(int prev, int nxt) {
    bool allowed;
    bool prev_open = (prev == 0) || (((prev - 1) & 3) >= 2);   // O, E-, S-
    if (prev_open) {
        allowed = (nxt == 0) || (((nxt - 1) & 3) == 0) || (((nxt - 1) & 3) == 3);
    } else {
        int ty = (prev - 1) >> 2;
        allowed = (nxt != 0) && (((nxt - 1) >> 2) == ty) &&
                  ((((nxt - 1) & 3) == 1) || (((nxt - 1) & 3) == 2));
    }
    return allowed ? 0.0f : -1e12f;
}

// Flat grid barrier: each CTA publishes its epoch; each of 128 threads polls one
// flag. __threadfence (gpu scope -> CCTL.IVALL) gives release before the flag
// store and L1 invalidation + acquire after the poll.
__device__ __forceinline__ void flatbar(int cta, int tid, unsigned e) {
    __syncthreads();
    __threadfence();
    if (tid == 0) g_flags[cta] = e;
    if (tid < NCTA) { while (g_flags[tid] < e) { } }
    __syncthreads();
    __threadfence();
}

// ---------------- K0: reset persistent state (graph replays) ----------------
__global__ void reset_state() {
    int i = blockIdx.x * blockDim.x + threadIdx.x;
    if (i < BB * HH) g_hbuf[0][i] = 0.0f;
    if (i < NCTA) g_flags[i] = 0u;
    if (i < BB) g_pt[i] = 0u;   // tag 0, pred 'O'
}

// ---------------- K1: label-embedding gate table ----------------
__global__ void build_table(const float* __restrict__ label_emb,
                            const float* __restrict__ W_ih,
                            const float* __restrict__ b_ih) {
    int j = blockIdx.x * blockDim.x + threadIdx.x;
    int l = blockIdx.y;
    if (j >= G3) return;
    const float* w = W_ih + (size_t)j * (EE + HH);
    const float* e = label_emb + l * EE;
    float s = b_ih[j];
#pragma unroll 8
    for (int k = 0; k < EE; k++) s += e[k] * w[k];
    g_tbl[l * G3 + j] = s;
}

// ---------------- K2: big SGEMM (double-buffered smem) ----------------
// g_gxw[m][n] = sum_k we[m][k] * W_ih[n][E+k],  m in [0,65536), n in [0,3072)
#define BM 128
#define BN 128
#define BK 8
__global__ __launch_bounds__(256, 2) void gxw_gemm(const float* __restrict__ A,
                                                   const float* __restrict__ Wih) {
    __shared__ float As[2][BK][BM + 4];
    __shared__ float Bs[2][BK][BN + 4];
    const int tid = threadIdx.x;
    const int m0 = blockIdx.y * BM;
    const int n0 = blockIdx.x * BN;
    const int lr = tid >> 1;           // 0..127
    const int lk = (tid & 1) * 4;      // 0 or 4
    const float* pA = A + (size_t)(m0 + lr) * HH + lk;
    const float* pB = Wih + (size_t)(n0 + lr) * (EE + HH) + EE + lk;

    float acc[8][8];
#pragma unroll
    for (int i = 0; i < 8; i++)
#pragma unroll
        for (int j = 0; j < 8; j++) acc[i][j] = 0.0f;

    const int tx = (tid & 15) * 8;
    const int ty = (tid >> 4) * 8;

    float4 fa = *(const float4*)pA;
    float4 fb = *(const float4*)pB;
    As[0][lk + 0][lr] = fa.x; As[0][lk + 1][lr] = fa.y;
    As[0][lk + 2][lr] = fa.z; As[0][lk + 3][lr] = fa.w;
    Bs[0][lk + 0][lr] = fb.x; Bs[0][lk + 1][lr] = fb.y;
    Bs[0][lk + 2][lr] = fb.z; Bs[0][lk + 3][lr] = fb.w;
    __syncthreads();

    int buf = 0;
    for (int k0 = 0; k0 < HH; k0 += BK) {
        bool has_next = (k0 + BK) < HH;
        if (has_next) {
            fa = *(const float4*)(pA + k0 + BK);
            fb = *(const float4*)(pB + k0 + BK);
        }
#pragma unroll
        for (int kk = 0; kk < BK; kk++) {
            float ar[8], br[8];
            *(float4*)&ar[0] = *(float4*)&As[buf][kk][ty];
            *(float4*)&ar[4] = *(float4*)&As[buf][kk][ty + 4];
            *(float4*)&br[0] = *(float4*)&Bs[buf][kk][tx];
            *(float4*)&br[4] = *(float4*)&Bs[buf][kk][tx + 4];
#pragma unroll
            for (int i = 0; i < 8; i++)
#pragma unroll
                for (int j = 0; j < 8; j++) acc[i][j] += ar[i] * br[j];
        }
        if (has_next) {
            int nb = buf ^ 1;
            As[nb][lk + 0][lr] = fa.x; As[nb][lk + 1][lr] = fa.y;
            As[nb][lk + 2][lr] = fa.z; As[nb][lk + 3][lr] = fa.w;
            Bs[nb][lk + 0][lr] = fb.x; Bs[nb][lk + 1][lr] = fb.y;
            Bs[nb][lk + 2][lr] = fb.z; Bs[nb][lk + 3][lr] = fb.w;
            __syncthreads();
            buf = nb;
        }
    }
#pragma unroll
    for (int i = 0; i < 8; i++) {
        size_t row = (size_t)(m0 + ty + i) * G3 + n0 + tx;
        *(float4*)&g_gxw[row]     = make_float4(acc[i][0], acc[i][1], acc[i][2], acc[i][3]);
        *(float4*)&g_gxw[row + 4] = make_float4(acc[i][4], acc[i][5], acc[i][6], acc[i][7]);
    }
}

// ---------------- K3: persistent recurrent kernel ----------------
// 128 CTAs x 128 threads. CTA c owns h-columns [c*8, c*8+8) (24 gate rows).
// Thread (g = tid>>5 in 0..3, mi = tid&31): 4 batches (mi+32i) x 2 h-cols
// (2g, 2g+1) x 3 gates = 24 accumulators. W reads are warp-broadcast LDS.
__global__ __launch_bounds__(128) void recurrent(const float* __restrict__ Whh,
                                                 const float* __restrict__ bhh,
                                                 const float* __restrict__ Wout,
                                                 const float* __restrict__ bout,
                                                 float* __restrict__ out) {
    __shared__ float sh_h[BB][SHP];        // 128 x 66
    __shared__ float sh_w[24][SHP];        // 24 gate rows x 66
    __shared__ float sh_row[HH];           // phase-2 hidden row
    __shared__ float sh_log[NL];

    const int tid = threadIdx.x;
    const int cta = blockIdx.x;
    const int g   = tid >> 5;              // 0..3
    const int mi  = tid & 31;
    const int base = cta * 8;
    const int c0 = 2 * g, c1 = 2 * g + 1;
    const int col0 = base + c0, col1 = base + c1;

    const float bhr0 = bhh[col0],          bhr1 = bhh[col1];
    const float bhz0 = bhh[HH + col0],     bhz1 = bhh[HH + col1];
    const float bhn0 = bhh[2 * HH + col0], bhn1 = bhh[2 * HH + col1];

    int cur = 0;
    for (int t = 0; t < TT; t++) {
        const float* __restrict__ hin = g_hbuf[cur];
        float* __restrict__ hout = g_hbuf[cur ^ 1];

        float ar0[4] = {0,0,0,0}, ar1[4] = {0,0,0,0};
        float az0[4] = {0,0,0,0}, az1[4] = {0,0,0,0};
        float an0[4] = {0,0,0,0}, an1[4] = {0,0,0,0};

        for (int kb = 0; kb < HH; kb += KC) {
            // stage h tile: 128 rows x 64 k  (2048 float4, 16/thread)
#pragma unroll
            for (int j = 0; j < 16; j++) {
                int f = tid + j * 128;
                int r = f >> 4, kq = f & 15;
                float4 v = *(const float4*)&hin[r * HH + kb + kq * 4];
                *(float2*)&sh_h[r][kq * 4]     = make_float2(v.x, v.y);
                *(float2*)&sh_h[r][kq * 4 + 2] = make_float2(v.z, v.w);
            }
            // stage W_hh tile: 24 gate rows x 64 k  (384 float4, 3/thread)
#pragma unroll
            for (int j = 0; j < 3; j++) {
                int f = tid + j * 128;
                int m = f >> 4, kq = f & 15;
                int grow = (m >> 3) * HH + base + (m & 7);
                float4 v = *(const float4*)&Whh[(size_t)grow * HH + kb + kq * 4];
                *(float2*)&sh_w[m][kq * 4]     = make_float2(v.x, v.y);
                *(float2*)&sh_w[m][kq * 4 + 2] = make_float2(v.z, v.w);
            }
            __syncthreads();
#pragma unroll 8
            for (int kk = 0; kk < KC; kk += 2) {
                float2 wr0 = *(float2*)&sh_w[c0][kk];
                float2 wr1 = *(float2*)&sh_w[c1][kk];
                float2 wz0 = *(float2*)&sh_w[8 + c0][kk];
                float2 wz1 = *(float2*)&sh_w[8 + c1][kk];
                float2 wn0 = *(float2*)&sh_w[16 + c0][kk];
                float2 wn1 = *(float2*)&sh_w[16 + c1][kk];
#pragma unroll
                for (int i = 0; i < 4; i++) {
                    float2 hv = *(float2*)&sh_h[mi + 32 * i][kk];
                    ar0[i] += hv.x * wr0.x + hv.y * wr0.y;
                    ar1[i] += hv.x * wr1.x + hv.y * wr1.y;
                    az0[i] += hv.x * wz0.x + hv.y * wz0.y;
                    az1[i] += hv.x * wz1.x + hv.y * wz1.y;
                    an0[i] += hv.x * wn0.x + hv.y * wn0.y;
                    an1[i] += hv.x * wn1.x + hv.y * wn1.y;
                }
            }
            __syncthreads();
        }

        // spin for prev-label tags (packed word: no ordering hazard), then GRU update
#pragma unroll
        for (int i = 0; i < 4; i++) {
            int b = mi + 32 * i;
            unsigned v = g_pt[b];
            while ((v >> 5) < (unsigned)t) v = g_pt[b];
            int pv = (int)(v & 31u);
            const float* tb = g_tbl + pv * G3;
            size_t grow = ((size_t)b * TT + t) * G3;

            float r0 = sigmoidf_(g_gxw[grow + col0] + tb[col0] + ar0[i] + bhr0);
            float z0 = sigmoidf_(g_gxw[grow + HH + col0] + tb[HH + col0] + az0[i] + bhz0);
            float n0 = tanhf(g_gxw[grow + 2 * HH + col0] + tb[2 * HH + col0] + r0 * (an0[i] + bhn0));
            float h0 = hin[b * HH + col0];
            hout[b * HH + col0] = (1.0f - z0) * n0 + z0 * h0;

            float r1 = sigmoidf_(g_gxw[grow + col1] + tb[col1] + ar1[i] + bhr1);
            float z1 = sigmoidf_(g_gxw[grow + HH + col1] + tb[HH + col1] + az1[i] + bhz1);
            float n1 = tanhf(g_gxw[grow + 2 * HH + col1] + tb[2 * HH + col1] + r1 * (an1[i] + bhn1));
            float h1 = hin[b * HH + col1];
            hout[b * HH + col1] = (1.0f - z1) * n1 + z1 * h1;
        }

        flatbar(cta, tid, (unsigned)(t + 1));

        // ---- phase 2: logits + masked argmax; CTA b handles batch row b ----
        {
            const int b = cta;
            const float* hb = &hout[b * HH];
            ((float4*)sh_row)[tid]       = ((const float4*)hb)[tid];
            ((float4*)sh_row)[tid + 128] = ((const float4*)hb)[tid + 128];
            __syncthreads();
            for (int l = g; l < NL; l += 4) {
                float s = 0.0f;
                const float* wo = Wout + (size_t)l * HH;
#pragma unroll 8
                for (int k = mi; k < HH; k += 32) s += sh_row[k] * __ldg(&wo[k]);
#pragma unroll
                for (int off = 16; off > 0; off >>= 1)
                    s += __shfl_down_sync(0xffffffffu, s, off);
                if (mi == 0) sh_log[l] = s;
            }
            __syncthreads();
            if (tid == 0) {
                int pv = (int)(g_pt[b] & 31u);
                float best = -INFINITY;
                int bi = 0;
                float* orow = out + ((size_t)b * TT + t) * NL;
#pragma unroll
                for (int l = 0; l < NL; l++) {
                    float v = sh_log[l] + bout[l] + maskval(pv, l);
                    orow[l] = v;
                    if (v > best) { best = v; bi = l; }
                }
                g_pt[b] = ((unsigned)(t + 1) << 5) | (unsigned)bi;
            }
        }
        cur ^= 1;
    }
}

// ---------------- launch ----------------
extern "C" void kernel_launch(void* const* d_in, const int* in_sizes, int n_in,
                              void* d_out, int out_size) {
    const float* we   = (const float*)d_in[0];  // [128,512,1024]
    const float* lemb = (const float*)d_in[1];  // [17,128]
    const float* wih  = (const float*)d_in[2];  // [3072,1152]
    const float* whh  = (const float*)d_in[3];  // [3072,1024]
    const float* bih  = (const float*)d_in[4];  // [3072]
    const float* bhh  = (const float*)d_in[5];  // [3072]
    const float* wout = (const float*)d_in[6];  // [17,1024]
    const float* bout = (const float*)d_in[7];  // [17]
    float* out = (float*)d_out;                 // [128,512,17]

    reset_state<<<512, 256>>>();
    build_table<<<dim3(G3 / 256, NL), 256>>>(lemb, wih, bih);
    gxw_gemm<<<dim3(G3 / BN, (BB * TT) / BM), 256>>>(we, wih);
    recurrent<<<NCTA, 128>>>(whh, bhh, wout, bout, out);
}

// round 4
// speedup vs baseline: 1.5393x; 1.5393x over previous
#include <cuda_runtime.h>
#include <math.h>

#define BB 128
#define TT 512
#define HH 1024
#define EE 128
#define NL 17
#define G3 3072        // 3*HH
#define NCTA 128       // persistent CTAs (co-resident, 1/SM)
#define KC 64          // K-block for recurrent GEMM
#define SHP 68         // sh_h/sh_w row stride: 4 mod 8 -> conflict-free LDS.128
#define GXP 132        // sh_gx row stride: 4 mod 32 -> conflict-free

// ---------------- device scratch ----------------
__device__ float g_gxw[201326592];            // [B][T][3H] precomputed w-part of gx
__device__ float g_tbl[NL * G3];              // label_emb @ W_ih[:, :E]^T + b_ih
__device__ float g_hbuf[2][BB * HH];          // double-buffered hidden state
__device__ volatile unsigned g_pt[BB];        // packed (tag<<5)|pred per batch
__device__ volatile unsigned g_flags[NCTA];   // flat barrier epoch flags

// ---------------- helpers ----------------
__device__ __forceinline__ float sigmoidf_(float x) { return 1.0f / (1.0f + expf(-x)); }

// IOBES transition mask. Labels: 0="O", 1+4*type+p with p: B=0,I=1,E=2,S=3.
__device__ __forceinline__ float maskval(int prev, int nxt) {
    bool allowed;
    bool prev_open = (prev == 0) || (((prev - 1) & 3) >= 2);   // O, E-, S-
    if (prev_open) {
        allowed = (nxt == 0) || (((nxt - 1) & 3) == 0) || (((nxt - 1) & 3) == 3);
    } else {
        int ty = (prev - 1) >> 2;
        allowed = (nxt != 0) && (((nxt - 1) >> 2) == ty) &&
                  ((((nxt - 1) & 3) == 1) || (((nxt - 1) & 3) == 2));
    }
    return allowed ? 0.0f : -1e12f;
}

// Flat grid barrier: CTA publishes epoch; threads tid<128 each poll one flag.
// __threadfence (gpu scope) = release before flag store; after the poll it
// invalidates L1D so subsequent plain loads see other CTAs' stores.
__device__ __forceinline__ void flatbar(int cta, int tid, unsigned e) {
    __syncthreads();
    __threadfence();
    if (tid == 0) g_flags[cta] = e;
    if (tid < NCTA) { while (g_flags[tid] < e) { } }
    __syncthreads();
    __threadfence();
}

// ---------------- K0: reset persistent state (graph replays) ----------------
__global__ void reset_state() {
    int i = blockIdx.x * blockDim.x + threadIdx.x;
    if (i < BB * HH) g_hbuf[0][i] = 0.0f;
    if (i < NCTA) g_flags[i] = 0u;
    if (i < BB) g_pt[i] = 0u;   // tag 0, pred 'O'
}

// ---------------- K1: label-embedding gate table ----------------
__global__ void build_table(const float* __restrict__ label_emb,
                            const float* __restrict__ W_ih,
                            const float* __restrict__ b_ih) {
    int j = blockIdx.x * blockDim.x + threadIdx.x;
    int l = blockIdx.y;
    if (j >= G3) return;
    const float* w = W_ih + (size_t)j * (EE + HH);
    const float* e = label_emb + l * EE;
    float s = b_ih[j];
#pragma unroll 8
    for (int k = 0; k < EE; k++) s += e[k] * w[k];
    g_tbl[l * G3 + j] = s;
}

// ---------------- K2: big SGEMM (double-buffered smem) ----------------
#define BM 128
#define BN 128
#define BK 8
__global__ __launch_bounds__(256) void gxw_gemm(const float* __restrict__ A,
                                                const float* __restrict__ Wih) {
    __shared__ float As[2][BK][BM + 4];
    __shared__ float Bs[2][BK][BN + 4];
    const int tid = threadIdx.x;
    const int m0 = blockIdx.y * BM;
    const int n0 = blockIdx.x * BN;
    const int lr = tid >> 1;           // 0..127
    const int lk = (tid & 1) * 4;      // 0 or 4
    const float* pA = A + (size_t)(m0 + lr) * HH + lk;
    const float* pB = Wih + (size_t)(n0 + lr) * (EE + HH) + EE + lk;

    float acc[8][8];
#pragma unroll
    for (int i = 0; i < 8; i++)
#pragma unroll
        for (int j = 0; j < 8; j++) acc[i][j] = 0.0f;

    const int tx = (tid & 15) * 8;
    const int ty = (tid >> 4) * 8;

    float4 fa = *(const float4*)pA;
    float4 fb = *(const float4*)pB;
    As[0][lk + 0][lr] = fa.x; As[0][lk + 1][lr] = fa.y;
    As[0][lk + 2][lr] = fa.z; As[0][lk + 3][lr] = fa.w;
    Bs[0][lk + 0][lr] = fb.x; Bs[0][lk + 1][lr] = fb.y;
    Bs[0][lk + 2][lr] = fb.z; Bs[0][lk + 3][lr] = fb.w;
    __syncthreads();

    int buf = 0;
    for (int k0 = 0; k0 < HH; k0 += BK) {
        bool has_next = (k0 + BK) < HH;
        if (has_next) {
            fa = *(const float4*)(pA + k0 + BK);
            fb = *(const float4*)(pB + k0 + BK);
        }
#pragma unroll
        for (int kk = 0; kk < BK; kk++) {
            float ar[8], br[8];
            *(float4*)&ar[0] = *(float4*)&As[buf][kk][ty];
            *(float4*)&ar[4] = *(float4*)&As[buf][kk][ty + 4];
            *(float4*)&br[0] = *(float4*)&Bs[buf][kk][tx];
            *(float4*)&br[4] = *(float4*)&Bs[buf][kk][tx + 4];
#pragma unroll
            for (int i = 0; i < 8; i++)
#pragma unroll
                for (int j = 0; j < 8; j++) acc[i][j] += ar[i] * br[j];
        }
        if (has_next) {
            int nb = buf ^ 1;
            As[nb][lk + 0][lr] = fa.x; As[nb][lk + 1][lr] = fa.y;
            As[nb][lk + 2][lr] = fa.z; As[nb][lk + 3][lr] = fa.w;
            Bs[nb][lk + 0][lr] = fb.x; Bs[nb][lk + 1][lr] = fb.y;
            Bs[nb][lk + 2][lr] = fb.z; Bs[nb][lk + 3][lr] = fb.w;
            __syncthreads();
            buf = nb;
        }
    }
#pragma unroll
    for (int i = 0; i < 8; i++) {
        size_t row = (size_t)(m0 + ty + i) * G3 + n0 + tx;
        *(float4*)&g_gxw[row]     = make_float4(acc[i][0], acc[i][1], acc[i][2], acc[i][3]);
        *(float4*)&g_gxw[row + 4] = make_float4(acc[i][4], acc[i][5], acc[i][6], acc[i][7]);
    }
}

// ---------------- K3: persistent recurrent kernel ----------------
// 128 CTAs x 256 threads. CTA c owns h-columns [c*8, c*8+8).
// Thread (g = tid>>5 in 0..7, mi = tid&31): 4 batches x 1 h-col x 3 gates.
__global__ __launch_bounds__(256) void recurrent(const float* __restrict__ Whh,
                                                 const float* __restrict__ bhh,
                                                 const float* __restrict__ Wout,
                                                 const float* __restrict__ bout,
                                                 float* __restrict__ out) {
    extern __shared__ float smem[];
    float* shh  = smem;                     // [128][SHP]
    float* shw  = shh + BB * SHP;           // [24][SHP]
    float* sgx  = shw + 24 * SHP;           // [24][GXP]
    float* srow = sgx + 24 * GXP;           // [1024]
    float* slog = srow + HH;                // [NL]

    const int tid = threadIdx.x;
    const int cta = blockIdx.x;
    const int g   = tid >> 5;              // 0..7
    const int mi  = tid & 31;
    const int base = cta * 8;
    const int col  = base + g;
    const int hold_kb = base & ~(KC - 1);
    const int hold_off = col - hold_kb;

    const float bhr = bhh[col];
    const float bhz = bhh[HH + col];
    const float bhn = bhh[2 * HH + col];

    int cur = 0;
    for (int t = 0; t < TT; t++) {
        const float* __restrict__ hin = g_hbuf[cur];
        float* __restrict__ hout = g_hbuf[cur ^ 1];

        // ---- coalesced gx staging: 3 gates x 8 cols x 128 b -> sgx ----
#pragma unroll
        for (int j = 0; j < 12; j++) {
            int f = tid + j * 256;                 // (gate, b, c)
            int gate = f >> 10;
            int b = (f >> 3) & 127;
            int c = f & 7;
            sgx[(gate * 8 + c) * GXP + b] =
                g_gxw[((size_t)b * TT + t) * G3 + gate * HH + base + c];
        }

        float ar[4] = {0, 0, 0, 0}, az[4] = {0, 0, 0, 0}, an[4] = {0, 0, 0, 0};
        float hold[4];

        for (int kb = 0; kb < HH; kb += KC) {
            // stage h tile: 128 rows x 64 k (2048 float4, 8/thread)
#pragma unroll
            for (int j = 0; j < 8; j++) {
                int f = tid + j * 256;
                int r = f >> 4, kq = f & 15;
                *(float4*)&shh[r * SHP + kq * 4] =
                    *(const float4*)&hin[r * HH + kb + kq * 4];
            }
            // stage W_hh tile: 24 gate rows x 64 k (384 float4)
            {
                int f = tid;
                if (f < 384) {
                    int m = f >> 4, kq = f & 15;
                    int wrow = (m >> 3) * HH + base + (m & 7);
                    *(float4*)&shw[m * SHP + kq * 4] =
                        *(const float4*)&Whh[(size_t)wrow * HH + kb + kq * 4];
                }
                f = tid + 256;
                if (f < 384) {
                    int m = f >> 4, kq = f & 15;
                    int wrow = (m >> 3) * HH + base + (m & 7);
                    *(float4*)&shw[m * SHP + kq * 4] =
                        *(const float4*)&Whh[(size_t)wrow * HH + kb + kq * 4];
                }
            }
            __syncthreads();

            if (kb == hold_kb) {
#pragma unroll
                for (int i = 0; i < 4; i++)
                    hold[i] = shh[(mi + 32 * i) * SHP + hold_off];
            }

#pragma unroll 4
            for (int kk = 0; kk < KC; kk += 4) {
                float4 wr = *(float4*)&shw[g * SHP + kk];
                float4 wz = *(float4*)&shw[(8 + g) * SHP + kk];
                float4 wn = *(float4*)&shw[(16 + g) * SHP + kk];
#pragma unroll
                for (int i = 0; i < 4; i++) {
                    float4 hv = *(float4*)&shh[(mi + 32 * i) * SHP + kk];
                    ar[i] += hv.x * wr.x + hv.y * wr.y + hv.z * wr.z + hv.w * wr.w;
                    az[i] += hv.x * wz.x + hv.y * wz.y + hv.z * wz.z + hv.w * wz.w;
                    an[i] += hv.x * wn.x + hv.y * wn.y + hv.z * wn.z + hv.w * wn.w;
                }
            }
            __syncthreads();
        }

        // ---- epilogue: spin for prev labels, GRU update ----
#pragma unroll
        for (int i = 0; i < 4; i++) {
            int b = mi + 32 * i;
            unsigned v = g_pt[b];
            while ((v >> 5) < (unsigned)t) v = g_pt[b];
            int pv = (int)(v & 31u);
            const float* tb = g_tbl + pv * G3;

            float xr = sgx[g * GXP + b]          + tb[col];
            float xz = sgx[(8 + g) * GXP + b]    + tb[HH + col];
            float xn = sgx[(16 + g) * GXP + b]   + tb[2 * HH + col];
            float r = sigmoidf_(xr + ar[i] + bhr);
            float z = sigmoidf_(xz + az[i] + bhz);
            float n = tanhf(xn + r * (an[i] + bhn));
            hout[b * HH + col] = (1.0f - z) * n + z * hold[i];
            ar[i] = 0.0f; az[i] = 0.0f; an[i] = 0.0f;
        }

        flatbar(cta, tid, (unsigned)(t + 1));

        // ---- phase 2: logits + masked argmax; CTA b handles batch row b ----
        {
            const int b = cta;
            ((float4*)srow)[tid] = ((const float4*)&hout[b * HH])[tid];
            __syncthreads();
            for (int l = g; l < NL; l += 8) {
                float s = 0.0f;
                const float* wo = Wout + (size_t)l * HH;
#pragma unroll 8
                for (int k = mi; k < HH; k += 32) s += srow[k] * __ldg(&wo[k]);
#pragma unroll
                for (int off = 16; off > 0; off >>= 1)
                    s += __shfl_down_sync(0xffffffffu, s, off);
                if (mi == 0) slog[l] = s;
            }
            __syncthreads();
            if (tid == 0) {
                int pv = (int)(g_pt[b] & 31u);
                float best = -INFINITY;
                int bi = 0;
                float* orow = out + ((size_t)b * TT + t) * NL;
#pragma unroll
                for (int l = 0; l < NL; l++) {
                    float v = slog[l] + bout[l] + maskval(pv, l);
                    orow[l] = v;
                    if (v > best) { best = v; bi = l; }
                }
                g_pt[b] = ((unsigned)(t + 1) << 5) | (unsigned)bi;
            }
            __syncthreads();
        }
        cur ^= 1;
    }
}

// ---------------- launch ----------------
extern "C" void kernel_launch(void* const* d_in, const int* in_sizes, int n_in,
                              void* d_out, int out_size) {
    const float* we   = (const float*)d_in[0];  // [128,512,1024]
    const float* lemb = (const float*)d_in[1];  // [17,128]
    const float* wih  = (const float*)d_in[2];  // [3072,1152]
    const float* whh  = (const float*)d_in[3];  // [3072,1024]
    const float* bih  = (const float*)d_in[4];  // [3072]
    const float* bhh  = (const float*)d_in[5];  // [3072]
    const float* wout = (const float*)d_in[6];  // [17,1024]
    const float* bout = (const float*)d_in[7];  // [17]
    float* out = (float*)d_out;                 // [128,512,17]

    const int shbytes = (BB * SHP + 24 * SHP + 24 * GXP + HH + 32) * 4;
    static int attr_done = 0;
    if (!attr_done) {
        cudaFuncSetAttribute(recurrent, cudaFuncAttributeMaxDynamicSharedMemorySize,
                             shbytes);
        attr_done = 1;
    }

    reset_state<<<512, 256>>>();
    build_table<<<dim3(G3 / 256, NL), 256>>>(lemb, wih, bih);
    gxw_gemm<<<dim3(G3 / BN, (BB * TT) / BM), 256>>>(we, wih);
    recurrent<<<NCTA, 256, shbytes>>>(whh, bhh, wout, bout, out);
}

// round 6
// speedup vs baseline: 1.6404x; 1.0657x over previous
#include <cuda_runtime.h>
#include <math.h>
#include <stdint.h>

#define BB 128
#define TT 512
#define HH 1024
#define EE 128
#define NL 17
#define G3 3072        // 3*HH
#define NCTA 128       // persistent CTAs (co-resident, 1/SM)
#define KC 64          // K-block for recurrent GEMM
#define SHP 68         // sh_h/sh_w row stride
#define GXP 132        // sh_gx row stride

// ---------------- device scratch ----------------
__device__ float g_gxw[201326592];            // [B][T][3H] precomputed w-part of gx
__device__ float g_tbl[NL * G3];              // label_emb @ W_ih[:, :E]^T + b_ih
__device__ float g_hbuf[2][BB * HH];          // double-buffered hidden state
__device__ volatile unsigned g_pt[BB];        // packed (tag<<5)|pred per batch
__device__ volatile unsigned g_flags[NCTA];   // flat barrier epoch flags

// ---------------- helpers ----------------
__device__ __forceinline__ float sigmoidf_(float x) { return 1.0f / (1.0f + expf(-x)); }

// IOBES transition mask. Labels: 0="O", 1+4*type+p with p: B=0,I=1,E=2,S=3.
__device__ __forceinline__ float maskval(int prev, int nxt) {
    bool allowed;
    bool prev_open = (prev == 0) || (((prev - 1) & 3) >= 2);   // O, E-, S-
    if (prev_open) {
        allowed = (nxt == 0) || (((nxt - 1) & 3) == 0) || (((nxt - 1) & 3) == 3);
    } else {
        int ty = (prev - 1) >> 2;
        allowed = (nxt != 0) && (((nxt - 1) >> 2) == ty) &&
                  ((((nxt - 1) & 3) == 1) || (((nxt - 1) & 3) == 2));
    }
    return allowed ? 0.0f : -1e12f;
}

// Flat grid barrier: CTA publishes epoch; threads tid<128 each poll one flag.
__device__ __forceinline__ void flatbar(int cta, int tid, unsigned e) {
    __syncthreads();
    __threadfence();
    if (tid == 0) g_flags[cta] = e;
    if (tid < NCTA) { while (g_flags[tid] < e) { } }
    __syncthreads();
    __threadfence();
}

// split fp32 -> (hi, lo) tf32 bit patterns for 3xTF32
__device__ __forceinline__ void split_tf32(float x, uint32_t& hi, uint32_t& lo) {
    asm("cvt.rna.tf32.f32 %0, %1;" : "=r"(hi) : "f"(x));
    float hif = __uint_as_float(hi);
    float lof = x - hif;
    asm("cvt.rna.tf32.f32 %0, %1;" : "=r"(lo) : "f"(lof));
}

__device__ __forceinline__ void mma_tf32(float* c, const uint32_t* a,
                                         uint32_t b0, uint32_t b1) {
    asm volatile(
        "mma.sync.aligned.m16n8k8.row.col.f32.tf32.tf32.f32 "
        "{%0,%1,%2,%3}, {%4,%5,%6,%7}, {%8,%9}, {%0,%1,%2,%3};"
        : "+f"(c[0]), "+f"(c[1]), "+f"(c[2]), "+f"(c[3])
        : "r"(a[0]), "r"(a[1]), "r"(a[2]), "r"(a[3]), "r"(b0), "r"(b1));
}

// ---------------- K0: reset persistent state ----------------
__global__ void reset_state() {
    int i = blockIdx.x * blockDim.x + threadIdx.x;
    if (i < BB * HH) g_hbuf[0][i] = 0.0f;
    if (i < NCTA) g_flags[i] = 0u;
    if (i < BB) g_pt[i] = 0u;   // tag 0, pred 'O'
}

// ---------------- K1: label-embedding gate table ----------------
__global__ void build_table(const float* __restrict__ label_emb,
                            const float* __restrict__ W_ih,
                            const float* __restrict__ b_ih) {
    int j = blockIdx.x * blockDim.x + threadIdx.x;
    int l = blockIdx.y;
    if (j >= G3) return;
    const float* w = W_ih + (size_t)j * (EE + HH);
    const float* e = label_emb + l * EE;
    float s = b_ih[j];
#pragma unroll 8
    for (int k = 0; k < EE; k++) s += e[k] * w[k];
    g_tbl[l * G3 + j] = s;
}

// ---------------- K2: big GEMM via 3xTF32 tensor-core MMA ----------------
// C[m][n] = sum_k A[m][k] * Wih[n][E+k].  CTA tile 128x256, warp 64x64.
#define KB 32
#define APAD 36
__global__ __launch_bounds__(256) void gxw_gemm_tc(const float* __restrict__ A,
                                                   const float* __restrict__ Wih) {
    extern __shared__ uint32_t su[];
    uint32_t* sAhi = su;                 // [128][36]
    uint32_t* sAlo = sAhi + 128 * APAD;
    uint32_t* sBhi = sAlo + 128 * APAD;  // [256][36]
    uint32_t* sBlo = sBhi + 256 * APAD;

    const int tid = threadIdx.x;
    const int lane = tid & 31;
    const int warp = tid >> 5;
    const int wm = (warp >> 2) * 64;     // warp m-offset (0/64)
    const int wn = (warp & 3) * 64;      // warp n-offset (0..192)
    const int m0 = blockIdx.y * 128;
    const int n0 = blockIdx.x * 256;

    const int lr = lane >> 2;            // 0..7
    const int lc = lane & 3;             // 0..3

    float acc[4][8][4];
#pragma unroll
    for (int i = 0; i < 4; i++)
#pragma unroll
        for (int j = 0; j < 8; j++)
#pragma unroll
            for (int q = 0; q < 4; q++) acc[i][j][q] = 0.0f;

    for (int kb = 0; kb < HH; kb += KB) {
        __syncthreads();
        // ---- stage A 128x32 (split) ----
#pragma unroll
        for (int jj = 0; jj < 4; jj++) {
            int idx = tid + jj * 256;          // 0..1023
            int r = idx >> 3, c4 = (idx & 7) * 4;
            float4 v = *(const float4*)&A[(size_t)(m0 + r) * HH + kb + c4];
            uint32_t h0, l0, h1, l1, h2, l2, h3, l3;
            split_tf32(v.x, h0, l0); split_tf32(v.y, h1, l1);
            split_tf32(v.z, h2, l2); split_tf32(v.w, h3, l3);
            *(uint4*)&sAhi[r * APAD + c4] = make_uint4(h0, h1, h2, h3);
            *(uint4*)&sAlo[r * APAD + c4] = make_uint4(l0, l1, l2, l3);
        }
        // ---- stage B 256x32 (split) ----
#pragma unroll
        for (int jj = 0; jj < 8; jj++) {
            int idx = tid + jj * 256;          // 0..2047
            int r = idx >> 3, c4 = (idx & 7) * 4;
            float4 v = *(const float4*)&Wih[(size_t)(n0 + r) * (EE + HH) + EE + kb + c4];
            uint32_t h0, l0, h1, l1, h2, l2, h3, l3;
            split_tf32(v.x, h0, l0); split_tf32(v.y, h1, l1);
            split_tf32(v.z, h2, l2); split_tf32(v.w, h3, l3);
            *(uint4*)&sBhi[r * APAD + c4] = make_uint4(h0, h1, h2, h3);
            *(uint4*)&sBlo[r * APAD + c4] = make_uint4(l0, l1, l2, l3);
        }
        __syncthreads();

#pragma unroll
        for (int ks = 0; ks < KB; ks += 8) {
            uint32_t ah[4][4], al[4][4];
#pragma unroll
            for (int i = 0; i < 4; i++) {
                int row = wm + i * 16 + lr;
                int cc = ks + lc;
                ah[i][0] = sAhi[row * APAD + cc];
                ah[i][1] = sAhi[(row + 8) * APAD + cc];
                ah[i][2] = sAhi[row * APAD + cc + 4];
                ah[i][3] = sAhi[(row + 8) * APAD + cc + 4];
                al[i][0] = sAlo[row * APAD + cc];
                al[i][1] = sAlo[(row + 8) * APAD + cc];
                al[i][2] = sAlo[row * APAD + cc + 4];
                al[i][3] = sAlo[(row + 8) * APAD + cc + 4];
            }
#pragma unroll
            for (int j = 0; j < 8; j++) {
                int cn = wn + j * 8 + lr;
                int ck = ks + lc;
                uint32_t bh0 = sBhi[cn * APAD + ck];
                uint32_t bh1 = sBhi[cn * APAD + ck + 4];
                uint32_t bl0 = sBlo[cn * APAD + ck];
                uint32_t bl1 = sBlo[cn * APAD + ck + 4];
#pragma unroll
                for (int i = 0; i < 4; i++) {
                    mma_tf32(acc[i][j], ah[i], bh0, bh1);
                    mma_tf32(acc[i][j], ah[i], bl0, bl1);
                    mma_tf32(acc[i][j], al[i], bh0, bh1);
                }
            }
        }
    }

    // ---- epilogue: C frags -> g_gxw ----
#pragma unroll
    for (int i = 0; i < 4; i++) {
#pragma unroll
        for (int j = 0; j < 8; j++) {
            int row = m0 + wm + i * 16 + lr;
            int cn = n0 + wn + j * 8 + lc * 2;
            *(float2*)&g_gxw[(size_t)row * G3 + cn] =
                make_float2(acc[i][j][0], acc[i][j][1]);
            *(float2*)&g_gxw[(size_t)(row + 8) * G3 + cn] =
                make_float2(acc[i][j][2], acc[i][j][3]);
        }
    }
}

// ---------------- K3: persistent recurrent kernel (R4, validated) ----------------
__global__ __launch_bounds__(256) void recurrent(const float* __restrict__ Whh,
                                                 const float* __restrict__ bhh,
                                                 const float* __restrict__ Wout,
                                                 const float* __restrict__ bout,
                                                 float* __restrict__ out) {
    extern __shared__ float smem[];
    float* shh  = smem;                     // [128][SHP]
    float* shw  = shh + BB * SHP;           // [24][SHP]
    float* sgx  = shw + 24 * SHP;           // [24][GXP]
    float* srow = sgx + 24 * GXP;           // [1024]
    float* slog = srow + HH;                // [NL]

    const int tid = threadIdx.x;
    const int cta = blockIdx.x;
    const int g   = tid >> 5;
    const int mi  = tid & 31;
    const int base = cta * 8;
    const int col  = base + g;
    const int hold_kb = base & ~(KC - 1);
    const int hold_off = col - hold_kb;

    const float bhr = bhh[col];
    const float bhz = bhh[HH + col];
    const float bhn = bhh[2 * HH + col];

    int cur = 0;
    for (int t = 0; t < TT; t++) {
        const float* __restrict__ hin = g_hbuf[cur];
        float* __restrict__ hout = g_hbuf[cur ^ 1];

#pragma unroll
        for (int j = 0; j < 12; j++) {
            int f = tid + j * 256;
            int gate = f >> 10;
            int b = (f >> 3) & 127;
            int c = f & 7;
            sgx[(gate * 8 + c) * GXP + b] =
                g_gxw[((size_t)b * TT + t) * G3 + gate * HH + base + c];
        }

        float ar[4] = {0, 0, 0, 0}, az[4] = {0, 0, 0, 0}, an[4] = {0, 0, 0, 0};
        float hold[4];

        for (int kb = 0; kb < HH; kb += KC) {
#pragma unroll
            for (int j = 0; j < 8; j++) {
                int f = tid + j * 256;
                int r = f >> 4, kq = f & 15;
                *(float4*)&shh[r * SHP + kq * 4] =
                    *(const float4*)&hin[r * HH + kb + kq * 4];
            }
            {
                int f = tid;
                if (f < 384) {
                    int m = f >> 4, kq = f & 15;
                    int wrow = (m >> 3) * HH + base + (m & 7);
                    *(float4*)&shw[m * SHP + kq * 4] =
                        *(const float4*)&Whh[(size_t)wrow * HH + kb + kq * 4];
                }
                f = tid + 256;
                if (f < 384) {
                    int m = f >> 4, kq = f & 15;
                    int wrow = (m >> 3) * HH + base + (m & 7);
                    *(float4*)&shw[m * SHP + kq * 4] =
                        *(const float4*)&Whh[(size_t)wrow * HH + kb + kq * 4];
                }
            }
            __syncthreads();

            if (kb == hold_kb) {
#pragma unroll
                for (int i = 0; i < 4; i++)
                    hold[i] = shh[(mi + 32 * i) * SHP + hold_off];
            }

#pragma unroll 4
            for (int kk = 0; kk < KC; kk += 4) {
                float4 wr = *(float4*)&shw[g * SHP + kk];
                float4 wz = *(float4*)&shw[(8 + g) * SHP + kk];
                float4 wn = *(float4*)&shw[(16 + g) * SHP + kk];
#pragma unroll
                for (int i = 0; i < 4; i++) {
                    float4 hv = *(float4*)&shh[(mi + 32 * i) * SHP + kk];
                    ar[i] += hv.x * wr.x + hv.y * wr.y + hv.z * wr.z + hv.w * wr.w;
                    az[i] += hv.x * wz.x + hv.y * wz.y + hv.z * wz.z + hv.w * wz.w;
                    an[i] += hv.x * wn.x + hv.y * wn.y + hv.z * wn.z + hv.w * wn.w;
                }
            }
            __syncthreads();
        }

#pragma unroll
        for (int i = 0; i < 4; i++) {
            int b = mi + 32 * i;
            unsigned v = g_pt[b];
            while ((v >> 5) < (unsigned)t) v = g_pt[b];
            int pv = (int)(v & 31u);
            const float* tb = g_tbl + pv * G3;

            float xr = sgx[g * GXP + b]        + tb[col];
            float xz = sgx[(8 + g) * GXP + b]  + tb[HH + col];
            float xn = sgx[(16 + g) * GXP + b] + tb[2 * HH + col];
            float r = sigmoidf_(xr + ar[i] + bhr);
            float z = sigmoidf_(xz + az[i] + bhz);
            float n = tanhf(xn + r * (an[i] + bhn));
            hout[b * HH + col] = (1.0f - z) * n + z * hold[i];
            ar[i] = 0.0f; az[i] = 0.0f; an[i] = 0.0f;
        }

        flatbar(cta, tid, (unsigned)(t + 1));

        {
            const int b = cta;
            ((float4*)srow)[tid] = ((const float4*)&hout[b * HH])[tid];
            __syncthreads();
            for (int l = g; l < NL; l += 8) {
                float s = 0.0f;
                const float* wo = Wout + (size_t)l * HH;
#pragma unroll 8
                for (int k = mi; k < HH; k += 32) s += srow[k] * __ldg(&wo[k]);
#pragma unroll
                for (int off = 16; off > 0; off >>= 1)
                    s += __shfl_down_sync(0xffffffffu, s, off);
                if (mi == 0) slog[l] = s;
            }
            __syncthreads();
            if (tid == 0) {
                int pv = (int)(g_pt[b] & 31u);
                float best = -INFINITY;
                int bi = 0;
                float* orow = out + ((size_t)b * TT + t) * NL;
#pragma unroll
                for (int l = 0; l < NL; l++) {
                    float v = slog[l] + bout[l] + maskval(pv, l);
                    orow[l] = v;
                    if (v > best) { best = v; bi = l; }
                }
                g_pt[b] = ((unsigned)(t + 1) << 5) | (unsigned)bi;
            }
            __syncthreads();
        }
        cur ^= 1;
    }
}

// ---------------- launch ----------------
extern "C" void kernel_launch(void* const* d_in, const int* in_sizes, int n_in,
                              void* d_out, int out_size) {
    const float* we   = (const float*)d_in[0];  // [128,512,1024]
    const float* lemb = (const float*)d_in[1];  // [17,128]
    const float* wih  = (const float*)d_in[2];  // [3072,1152]
    const float* whh  = (const float*)d_in[3];  // [3072,1024]
    const float* bih  = (const float*)d_in[4];  // [3072]
    const float* bhh  = (const float*)d_in[5];  // [3072]
    const float* wout = (const float*)d_in[6];  // [17,1024]
    const float* bout = (const float*)d_in[7];  // [17]
    float* out = (float*)d_out;                 // [128,512,17]

    const int sh_rec  = (BB * SHP + 24 * SHP + 24 * GXP + HH + 32) * 4;
    const int sh_gemm = (2 * 128 * APAD + 2 * 256 * APAD) * 4;   // 110,592 B
    cudaFuncSetAttribute(recurrent, cudaFuncAttributeMaxDynamicSharedMemorySize,
                         sh_rec);
    cudaFuncSetAttribute(gxw_gemm_tc, cudaFuncAttributeMaxDynamicSharedMemorySize,
                         sh_gemm);

    reset_state<<<512, 256>>>();
    build_table<<<dim3(G3 / 256, NL), 256>>>(lemb, wih, bih);
    gxw_gemm_tc<<<dim3(G3 / 256, (BB * TT) / 128), 256, sh_gemm>>>(we, wih);
    recurrent<<<NCTA, 256, sh_rec>>>(whh, bhh, wout, bout, out);
}

// round 9
// speedup vs baseline: 1.9793x; 1.2066x over previous
#include <cuda_runtime.h>
#include <math.h>
#include <stdint.h>

#define BB 128
#define TT 512
#define HH 1024
#define EE 128
#define NL 17
#define G3 3072
#define NCTA 128
#define KC 64          // h k-block
#define SHP 68         // h slab row stride (floats)
#define GXP 132        // sgx row stride

// ---------------- device scratch ----------------
__device__ float g_gxw[201326592];            // [B][T][3H]
__device__ uint32_t g_Ahi[67108864];          // we hi  [65536][1024]
__device__ uint32_t g_Alo[67108864];          // we lo
__device__ uint32_t g_Bhi[3145728];           // Wih[:,E:] hi [3072][1024]
__device__ uint32_t g_Blo[3145728];
__device__ float g_tbl[NL * G3];
__device__ float g_hbuf[2][BB * HH];
__device__ volatile unsigned g_pt[BB];        // packed (tag<<5)|pred
__device__ volatile unsigned g_flags[NCTA];

// ---------------- helpers ----------------
__device__ __forceinline__ float sigmoidf_(float x) { return 1.0f / (1.0f + expf(-x)); }

__device__ __forceinline__ float maskval(int prev, int nxt) {
    bool allowed;
    bool prev_open = (prev == 0) || (((prev - 1) & 3) >= 2);   // O, E-, S-
    if (prev_open) {
        allowed = (nxt == 0) || (((nxt - 1) & 3) == 0) || (((nxt - 1) & 3) == 3);
    } else {
        int ty = (prev - 1) >> 2;
        allowed = (nxt != 0) && (((nxt - 1) >> 2) == ty) &&
                  ((((nxt - 1) & 3) == 1) || (((nxt - 1) & 3) == 2));
    }
    return allowed ? 0.0f : -1e12f;
}

__device__ __forceinline__ void flatbar(int cta, int tid, unsigned e) {
    __syncthreads();
    __threadfence();
    if (tid == 0) g_flags[cta] = e;
    if (tid < NCTA) { while (g_flags[tid] < e) { } }
    __syncthreads();
    __threadfence();
}

__device__ __forceinline__ void split_tf32(float x, uint32_t& hi, uint32_t& lo) {
    asm("cvt.rna.tf32.f32 %0, %1;" : "=r"(hi) : "f"(x));
    float hif = __uint_as_float(hi);
    float lof = x - hif;
    asm("cvt.rna.tf32.f32 %0, %1;" : "=r"(lo) : "f"(lof));
}

__device__ __forceinline__ void mma_tf32(float* c, const uint32_t* a,
                                         uint32_t b0, uint32_t b1) {
    asm volatile(
        "mma.sync.aligned.m16n8k8.row.col.f32.tf32.tf32.f32 "
        "{%0,%1,%2,%3}, {%4,%5,%6,%7}, {%8,%9}, {%0,%1,%2,%3};"
        : "+f"(c[0]), "+f"(c[1]), "+f"(c[2]), "+f"(c[3])
        : "r"(a[0]), "r"(a[1]), "r"(a[2]), "r"(a[3]), "r"(b0), "r"(b1));
}

// ---------------- K0: reset persistent state ----------------
__global__ void reset_state() {
    int i = blockIdx.x * blockDim.x + threadIdx.x;
    if (i < BB * HH) g_hbuf[0][i] = 0.0f;
    if (i < NCTA) g_flags[i] = 0u;
    if (i < BB) g_pt[i] = 0u;
}

// ---------------- K1: label-embedding gate table ----------------
__global__ void build_table(const float* __restrict__ label_emb,
                            const float* __restrict__ W_ih,
                            const float* __restrict__ b_ih) {
    int j = blockIdx.x * blockDim.x + threadIdx.x;
    int l = blockIdx.y;
    if (j >= G3) return;
    const float* w = W_ih + (size_t)j * (EE + HH);
    const float* e = label_emb + l * EE;
    float s = b_ih[j];
#pragma unroll 8
    for (int k = 0; k < EE; k++) s += e[k] * w[k];
    g_tbl[l * G3 + j] = s;
}

// ---------------- pre-split kernels (gxw operands, rna) ----------------
__global__ void presplit_A(const float* __restrict__ we) {
    size_t i = (size_t)blockIdx.x * blockDim.x + threadIdx.x;
    size_t stride = (size_t)gridDim.x * blockDim.x;
    size_t n4 = (size_t)BB * TT * HH / 4;
    for (; i < n4; i += stride) {
        float4 v = ((const float4*)we)[i];
        uint4 hi, lo;
        split_tf32(v.x, hi.x, lo.x); split_tf32(v.y, hi.y, lo.y);
        split_tf32(v.z, hi.z, lo.z); split_tf32(v.w, hi.w, lo.w);
        ((uint4*)g_Ahi)[i] = hi;
        ((uint4*)g_Alo)[i] = lo;
    }
}

__global__ void presplit_B(const float* __restrict__ wih) {
    size_t i = (size_t)blockIdx.x * blockDim.x + threadIdx.x;
    size_t stride = (size_t)gridDim.x * blockDim.x;
    size_t n4 = (size_t)G3 * HH / 4;
    for (; i < n4; i += stride) {
        size_t r = i >> 8;
        size_t c4 = (i & 255) * 4;
        float4 v = *(const float4*)&wih[r * (EE + HH) + EE + c4];
        uint4 hi, lo;
        split_tf32(v.x, hi.x, lo.x); split_tf32(v.y, hi.y, lo.y);
        split_tf32(v.z, hi.z, lo.z); split_tf32(v.w, hi.w, lo.w);
        *(uint4*)&g_Bhi[r * HH + c4] = hi;
        *(uint4*)&g_Blo[r * HH + c4] = lo;
    }
}

// ---------------- K2: big GEMM, 3xTF32 TC, pre-split operands ----------------
// Bit-identical output to the R6-validated TC GEMM.
#define KB 32
#define APAD 36
__global__ __launch_bounds__(256) void gxw_gemm_tc(void) {
    extern __shared__ uint32_t su[];
    uint32_t* sAhi = su;
    uint32_t* sAlo = sAhi + 128 * APAD;
    uint32_t* sBhi = sAlo + 128 * APAD;
    uint32_t* sBlo = sBhi + 256 * APAD;

    const int tid = threadIdx.x;
    const int lane = tid & 31;
    const int warp = tid >> 5;
    const int wm = (warp >> 2) * 64;
    const int wn = (warp & 3) * 64;
    const int m0 = blockIdx.y * 128;
    const int n0 = blockIdx.x * 256;
    const int lr = lane >> 2;
    const int lc = lane & 3;

    float acc[4][8][4];
#pragma unroll
    for (int i = 0; i < 4; i++)
#pragma unroll
        for (int j = 0; j < 8; j++)
#pragma unroll
            for (int q = 0; q < 4; q++) acc[i][j][q] = 0.0f;

    for (int kb = 0; kb < HH; kb += KB) {
        __syncthreads();
#pragma unroll
        for (int jj = 0; jj < 4; jj++) {
            int idx = tid + jj * 256;
            int r = idx >> 3, c4 = (idx & 7) * 4;
            size_t src = (size_t)(m0 + r) * HH + kb + c4;
            *(uint4*)&sAhi[r * APAD + c4] = *(const uint4*)&g_Ahi[src];
            *(uint4*)&sAlo[r * APAD + c4] = *(const uint4*)&g_Alo[src];
        }
#pragma unroll
        for (int jj = 0; jj < 8; jj++) {
            int idx = tid + jj * 256;
            int r = idx >> 3, c4 = (idx & 7) * 4;
            size_t src = (size_t)(n0 + r) * HH + kb + c4;
            *(uint4*)&sBhi[r * APAD + c4] = *(const uint4*)&g_Bhi[src];
            *(uint4*)&sBlo[r * APAD + c4] = *(const uint4*)&g_Blo[src];
        }
        __syncthreads();

#pragma unroll
        for (int ks = 0; ks < KB; ks += 8) {
            uint32_t ah[4][4], al[4][4];
#pragma unroll
            for (int i = 0; i < 4; i++) {
                int row = wm + i * 16 + lr;
                int cc = ks + lc;
                ah[i][0] = sAhi[row * APAD + cc];
                ah[i][1] = sAhi[(row + 8) * APAD + cc];
                ah[i][2] = sAhi[row * APAD + cc + 4];
                ah[i][3] = sAhi[(row + 8) * APAD + cc + 4];
                al[i][0] = sAlo[row * APAD + cc];
                al[i][1] = sAlo[(row + 8) * APAD + cc];
                al[i][2] = sAlo[row * APAD + cc + 4];
                al[i][3] = sAlo[(row + 8) * APAD + cc + 4];
            }
#pragma unroll
            for (int j = 0; j < 8; j++) {
                int cn = wn + j * 8 + lr;
                int ck = ks + lc;
                uint32_t bh0 = sBhi[cn * APAD + ck];
                uint32_t bh1 = sBhi[cn * APAD + ck + 4];
                uint32_t bl0 = sBlo[cn * APAD + ck];
                uint32_t bl1 = sBlo[cn * APAD + ck + 4];
#pragma unroll
                for (int i = 0; i < 4; i++) {
                    mma_tf32(acc[i][j], ah[i], bh0, bh1);
                    mma_tf32(acc[i][j], ah[i], bl0, bl1);
                    mma_tf32(acc[i][j], al[i], bh0, bh1);
                }
            }
        }
    }

#pragma unroll
    for (int i = 0; i < 4; i++) {
#pragma unroll
        for (int j = 0; j < 8; j++) {
            int row = m0 + wm + i * 16 + lr;
            int cn = n0 + wn + j * 8 + lc * 2;
            *(float2*)&g_gxw[(size_t)row * G3 + cn] =
                make_float2(acc[i][j][0], acc[i][j][1]);
            *(float2*)&g_gxw[(size_t)(row + 8) * G3 + cn] =
                make_float2(acc[i][j][2], acc[i][j][3]);
        }
    }
}

// ---------------- K3: persistent recurrent (R6 fp32 arithmetic, verbatim) ----
// 128 CTAs x 256 threads. CTA c owns h-cols [8c, 8c+8).
// Thread (g=tid>>5, mi=tid&31): 4 batches x 1 col x 3 gates, sequential-k FMA.
// New vs R6: W resident in smem for all steps; double-buffered h slabs with
// register prefetch and ONE __syncthreads per k-block.
__global__ __launch_bounds__(256) void recurrent(const float* __restrict__ Whh,
                                                 const float* __restrict__ bhh,
                                                 const float* __restrict__ Wout,
                                                 const float* __restrict__ bout,
                                                 float* __restrict__ out) {
    extern __shared__ float smem[];
    float* shw  = smem;                     // [24][1024]
    float* shh  = shw + 24 * 1024;          // [2][128][SHP]
    float* sgx  = shh + 2 * BB * SHP;       // [24][GXP]
    float* srow = sgx + 24 * GXP;           // [1024]
    __shared__ float slog[NL];

    const int tid = threadIdx.x;
    const int cta = blockIdx.x;
    const int g   = tid >> 5;
    const int mi  = tid & 31;
    const int base = cta * 8;
    const int col  = base + g;
    const int hold_kb = base & ~(KC - 1);
    const int hold_off = col - hold_kb;

    // one-time: resident W (24 gate rows x 1024)
    for (int f4 = tid; f4 < 24 * 256; f4 += 256) {
        int m = f4 >> 8;                 // 0..23
        int q = f4 & 255;                // float4 within row
        int wrow = (m >> 3) * HH + base + (m & 7);
        *(float4*)&shw[m * 1024 + q * 4] =
            *(const float4*)&Whh[(size_t)wrow * HH + q * 4];
    }
    const float bhr = bhh[col];
    const float bhz = bhh[HH + col];
    const float bhn = bhh[2 * HH + col];
    __syncthreads();

    const int sr = tid >> 4;             // staging row pair base: f=tid+j*256
    const int skq = tid & 15;            // (r = f>>4, kq = f&15)

    int cur = 0;
    for (int t = 0; t < TT; t++) {
        const float* __restrict__ hin = g_hbuf[cur];
        float* __restrict__ hout = g_hbuf[cur ^ 1];

        // ---- coalesced gx staging (R6 verbatim) ----
#pragma unroll
        for (int j = 0; j < 12; j++) {
            int f = tid + j * 256;
            int gate = f >> 10;
            int b = (f >> 3) & 127;
            int c = f & 7;
            sgx[(gate * 8 + c) * GXP + b] =
                g_gxw[((size_t)b * TT + t) * G3 + gate * HH + base + c];
        }

        // ---- prefetch + store h block 0 ----
        float4 pf[8];
#pragma unroll
        for (int j = 0; j < 8; j++) {
            int f = tid + j * 256;
            int r = f >> 4, kq = f & 15;
            pf[j] = *(const float4*)&hin[r * HH + kq * 4];
        }
#pragma unroll
        for (int j = 0; j < 8; j++) {
            int f = tid + j * 256;
            int r = f >> 4, kq = f & 15;
            *(float4*)&shh[r * SHP + kq * 4] = pf[j];
        }
        __syncthreads();

        float ar[4] = {0, 0, 0, 0}, az[4] = {0, 0, 0, 0}, an[4] = {0, 0, 0, 0};
        float hold[4];

        for (int kb = 0; kb < HH; kb += KC) {
            const int buf = (kb >> 6) & 1;
            float* hb = shh + buf * BB * SHP;

            // prefetch next block into regs (overlaps compute)
            if (kb + KC < HH) {
#pragma unroll
                for (int j = 0; j < 8; j++) {
                    int f = tid + j * 256;
                    int r = f >> 4, kq = f & 15;
                    pf[j] = *(const float4*)&hin[r * HH + kb + KC + kq * 4];
                }
            }

            if (kb == hold_kb) {
#pragma unroll
                for (int i = 0; i < 4; i++)
                    hold[i] = hb[(mi + 32 * i) * SHP + hold_off];
            }

#pragma unroll 4
            for (int kk = 0; kk < KC; kk += 4) {
                float4 wr = *(float4*)&shw[g * 1024 + kb + kk];
                float4 wz = *(float4*)&shw[(8 + g) * 1024 + kb + kk];
                float4 wn = *(float4*)&shw[(16 + g) * 1024 + kb + kk];
#pragma unroll
                for (int i = 0; i < 4; i++) {
                    float4 hv = *(float4*)&hb[(mi + 32 * i) * SHP + kk];
                    ar[i] += hv.x * wr.x + hv.y * wr.y + hv.z * wr.z + hv.w * wr.w;
                    az[i] += hv.x * wz.x + hv.y * wz.y + hv.z * wz.z + hv.w * wz.w;
                    an[i] += hv.x * wn.x + hv.y * wn.y + hv.z * wn.z + hv.w * wn.w;
                }
            }

            if (kb + KC < HH) {
                float* nb = shh + (buf ^ 1) * BB * SHP;
#pragma unroll
                for (int j = 0; j < 8; j++) {
                    int f = tid + j * 256;
                    int r = f >> 4, kq = f & 15;
                    *(float4*)&nb[r * SHP + kq * 4] = pf[j];
                }
            }
            __syncthreads();
        }

        // ---- epilogue (R6 verbatim): spin for prev labels, GRU update ----
#pragma unroll
        for (int i = 0; i < 4; i++) {
            int b = mi + 32 * i;
            unsigned v = g_pt[b];
            while ((v >> 5) < (unsigned)t) v = g_pt[b];
            int pv = (int)(v & 31u);
            const float* tb = g_tbl + pv * G3;

            float xr = sgx[g * GXP + b]        + tb[col];
            float xz = sgx[(8 + g) * GXP + b]  + tb[HH + col];
            float xn = sgx[(16 + g) * GXP + b] + tb[2 * HH + col];
            float r = sigmoidf_(xr + ar[i] + bhr);
            float z = sigmoidf_(xz + az[i] + bhz);
            float n = tanhf(xn + r * (an[i] + bhn));
            hout[b * HH + col] = (1.0f - z) * n + z * hold[i];
            ar[i] = 0.0f; az[i] = 0.0f; an[i] = 0.0f;
        }

        flatbar(cta, tid, (unsigned)(t + 1));

        // ---- phase 2 (R6 verbatim): logits + masked argmax ----
        {
            const int b = cta;
            ((float4*)srow)[tid] = ((const float4*)&hout[b * HH])[tid];
            __syncthreads();
            for (int l = g; l < NL; l += 8) {
                float s = 0.0f;
                const float* wo = Wout + (size_t)l * HH;
#pragma unroll 8
                for (int k = mi; k < HH; k += 32) s += srow[k] * __ldg(&wo[k]);
#pragma unroll
                for (int off = 16; off > 0; off >>= 1)
                    s += __shfl_down_sync(0xffffffffu, s, off);
                if (mi == 0) slog[l] = s;
            }
            __syncthreads();
            if (tid == 0) {
                int pv = (int)(g_pt[b] & 31u);
                float best = -INFINITY;
                int bi = 0;
                float* orow = out + ((size_t)b * TT + t) * NL;
#pragma unroll
                for (int l = 0; l < NL; l++) {
                    float v = slog[l] + bout[l] + maskval(pv, l);
                    orow[l] = v;
                    if (v > best) { best = v; bi = l; }
                }
                g_pt[b] = ((unsigned)(t + 1) << 5) | (unsigned)bi;
            }
            __syncthreads();
        }
        cur ^= 1;
    }
}

// ---------------- launch ----------------
extern "C" void kernel_launch(void* const* d_in, const int* in_sizes, int n_in,
                              void* d_out, int out_size) {
    const float* we   = (const float*)d_in[0];
    const float* lemb = (const float*)d_in[1];
    const float* wih  = (const float*)d_in[2];
    const float* whh  = (const float*)d_in[3];
    const float* bih  = (const float*)d_in[4];
    const float* bhh  = (const float*)d_in[5];
    const float* wout = (const float*)d_in[6];
    const float* bout = (const float*)d_in[7];
    float* out = (float*)d_out;

    const int sh_gemm = (2 * 128 * APAD + 2 * 256 * APAD) * 4;            // 110,592 B
    const int sh_rec  = (24 * 1024 + 2 * BB * SHP + 24 * GXP + 1024) * 4; // 184,704 B
    cudaFuncSetAttribute(gxw_gemm_tc, cudaFuncAttributeMaxDynamicSharedMemorySize,
                         sh_gemm);
    cudaFuncSetAttribute(recurrent, cudaFuncAttributeMaxDynamicSharedMemorySize,
                         sh_rec);

    reset_state<<<512, 256>>>();
    build_table<<<dim3(G3 / 256, NL), 256>>>(lemb, wih, bih);
    presplit_A<<<4096, 256>>>(we);
    presplit_B<<<768, 256>>>(wih);
    gxw_gemm_tc<<<dim3(G3 / 256, (BB * TT) / 128), 256, sh_gemm>>>();
    recurrent<<<NCTA, 256, sh_rec>>>(whh, bhh, wout, bout, out);
}